// round 1
// baseline (speedup 1.0000x reference)
#include <cuda_runtime.h>
#include <math.h>

#define D_MODEL   1024
#define NUM_HEADS 16
#define HEAD_DIM  64
#define B_        2
#define T_        2048
#define BT        (B_ * T_)           // 4096
#define BHEADS    (B_ * NUM_HEADS)    // 32

// Scratch (allocation-free rule: __device__ globals)
__device__ float g_q[BHEADS * T_ * HEAD_DIM];   // [b,h,t,d]
__device__ float g_k[BHEADS * T_ * HEAD_DIM];
__device__ float g_v[BHEADS * T_ * HEAD_DIM];
__device__ float g_ao[BT * D_MODEL];            // attention output, [b,t,D]

// ---------------------------------------------------------------------------
// Kernel 1: QKV = x @ Wqkv + bqkv, scattered into q/k/v in [B,H,T,hd] layout.
// M=4096, N=3072, K=1024. Tile 64x64x16, 256 threads, 4x4 per thread.
// ---------------------------------------------------------------------------
__global__ void qkv_gemm(const float* __restrict__ X,
                         const float* __restrict__ W,
                         const float* __restrict__ bias) {
    const int BM = 64, BN = 64, BK = 16;
    __shared__ float As[BM][BK + 1];
    __shared__ float Bs[BK][BN];

    int tid = threadIdx.x;
    int tx = tid & 15, ty = tid >> 4;
    int row0 = blockIdx.y * BM;
    int col0 = blockIdx.x * BN;

    float acc[4][4] = {};

    for (int kt = 0; kt < D_MODEL; kt += BK) {
        #pragma unroll
        for (int i = tid; i < BM * BK; i += 256) {
            int m = i >> 4, kk = i & 15;
            As[m][kk] = X[(size_t)(row0 + m) * D_MODEL + kt + kk];
        }
        #pragma unroll
        for (int i = tid; i < BK * BN; i += 256) {
            int kk = i >> 6, n = i & 63;
            Bs[kk][n] = W[(size_t)(kt + kk) * (3 * D_MODEL) + col0 + n];
        }
        __syncthreads();
        #pragma unroll
        for (int kk = 0; kk < BK; kk++) {
            float a[4], b[4];
            #pragma unroll
            for (int i = 0; i < 4; i++) a[i] = As[ty * 4 + i][kk];
            #pragma unroll
            for (int j = 0; j < 4; j++) b[j] = Bs[kk][tx * 4 + j];
            #pragma unroll
            for (int i = 0; i < 4; i++)
                #pragma unroll
                for (int j = 0; j < 4; j++)
                    acc[i][j] += a[i] * b[j];
        }
        __syncthreads();
    }

    #pragma unroll
    for (int i = 0; i < 4; i++) {
        int r = row0 + ty * 4 + i;
        int b = r / T_, t = r % T_;
        #pragma unroll
        for (int j = 0; j < 4; j++) {
            int c = col0 + tx * 4 + j;
            float val = acc[i][j] + bias[c];
            int which = c / D_MODEL;
            int d = c % D_MODEL;
            int h = d / HEAD_DIM, dd = d % HEAD_DIM;
            float* dst = (which == 0) ? g_q : ((which == 1) ? g_k : g_v);
            dst[((size_t)(b * NUM_HEADS + h) * T_ + t) * HEAD_DIM + dd] = val;
        }
    }
}

// ---------------------------------------------------------------------------
// Kernel 2: scores[bh, t, s] = (q[bh,t,:] . k[bh,s,:]) * 1/8
// Written directly into the weights region of d_out. Per-head 64x64 tiles,
// full K=64 in one shot (Q,K tiles resident in smem).
// ---------------------------------------------------------------------------
__global__ void scores_gemm(float* __restrict__ wts) {
    __shared__ float Qs[64][65];
    __shared__ float Ks[64][65];

    int tid = threadIdx.x;
    int tx = tid & 15, ty = tid >> 4;
    int bh = blockIdx.z;
    int row0 = blockIdx.y * 64;   // query index t
    int col0 = blockIdx.x * 64;   // key index s

    const float* qb = g_q + (size_t)bh * T_ * HEAD_DIM;
    const float* kb = g_k + (size_t)bh * T_ * HEAD_DIM;

    #pragma unroll
    for (int i = tid; i < 64 * 64; i += 256) {
        int m = i >> 6, kk = i & 63;
        Qs[m][kk] = qb[(size_t)(row0 + m) * HEAD_DIM + kk];
        Ks[m][kk] = kb[(size_t)(col0 + m) * HEAD_DIM + kk];
    }
    __syncthreads();

    float acc[4][4] = {};
    #pragma unroll 16
    for (int kk = 0; kk < 64; kk++) {
        float a[4], b[4];
        #pragma unroll
        for (int i = 0; i < 4; i++) a[i] = Qs[ty * 4 + i][kk];
        #pragma unroll
        for (int j = 0; j < 4; j++) b[j] = Ks[tx * 4 + j][kk];
        #pragma unroll
        for (int i = 0; i < 4; i++)
            #pragma unroll
            for (int j = 0; j < 4; j++)
                acc[i][j] += a[i] * b[j];
    }

    float* out = wts + (size_t)bh * T_ * T_;
    const float scale = 0.125f;  // 1/sqrt(64)
    #pragma unroll
    for (int i = 0; i < 4; i++) {
        size_t rbase = (size_t)(row0 + ty * 4 + i) * T_;
        #pragma unroll
        for (int j = 0; j < 4; j++)
            out[rbase + col0 + tx * 4 + j] = acc[i][j] * scale;
    }
}

// ---------------------------------------------------------------------------
// Kernel 3: in-place row softmax over the last dim (T_=2048) of weights.
// One block (256 threads) per row; 8 elements/thread held in registers.
// ---------------------------------------------------------------------------
__global__ void softmax_rows(float* __restrict__ wts) {
    size_t row = blockIdx.x;
    float* p = wts + row * (size_t)T_;
    int tid = threadIdx.x;
    int lane = tid & 31, warp = tid >> 5;

    __shared__ float red[8];

    float r[8];
    float mx = -INFINITY;
    #pragma unroll
    for (int j = 0; j < 8; j++) {
        r[j] = p[tid + j * 256];
        mx = fmaxf(mx, r[j]);
    }
    #pragma unroll
    for (int o = 16; o > 0; o >>= 1)
        mx = fmaxf(mx, __shfl_xor_sync(0xffffffffu, mx, o));
    if (lane == 0) red[warp] = mx;
    __syncthreads();
    float rowmax = red[0];
    #pragma unroll
    for (int w = 1; w < 8; w++) rowmax = fmaxf(rowmax, red[w]);
    __syncthreads();

    float s = 0.f;
    #pragma unroll
    for (int j = 0; j < 8; j++) {
        r[j] = __expf(r[j] - rowmax);
        s += r[j];
    }
    #pragma unroll
    for (int o = 16; o > 0; o >>= 1)
        s += __shfl_xor_sync(0xffffffffu, s, o);
    if (lane == 0) red[warp] = s;
    __syncthreads();
    float tot = 0.f;
    #pragma unroll
    for (int w = 0; w < 8; w++) tot += red[w];
    float inv = 1.f / tot;

    #pragma unroll
    for (int j = 0; j < 8; j++)
        p[tid + j * 256] = r[j] * inv;
}

// ---------------------------------------------------------------------------
// Kernel 4: out[bh, t, dd] = sum_s weights[bh,t,s] * v[bh,s,dd]
// M=2048 (per head), N=64, K=2048. Tile 64x64x16. Writes [B,T,D] layout.
// ---------------------------------------------------------------------------
__global__ void av_gemm(const float* __restrict__ wts) {
    const int BM = 64, BN = 64, BK = 16;
    __shared__ float As[BM][BK + 1];
    __shared__ float Bs[BK][BN];

    int tid = threadIdx.x;
    int tx = tid & 15, ty = tid >> 4;
    int bh = blockIdx.z;
    int row0 = blockIdx.y * BM;

    const float* wb = wts + (size_t)bh * T_ * T_;
    const float* vb = g_v + (size_t)bh * T_ * HEAD_DIM;

    float acc[4][4] = {};
    for (int kt = 0; kt < T_; kt += BK) {
        #pragma unroll
        for (int i = tid; i < BM * BK; i += 256) {
            int m = i >> 4, kk = i & 15;
            As[m][kk] = wb[(size_t)(row0 + m) * T_ + kt + kk];
        }
        #pragma unroll
        for (int i = tid; i < BK * BN; i += 256) {
            int kk = i >> 6, n = i & 63;
            Bs[kk][n] = vb[(size_t)(kt + kk) * HEAD_DIM + n];
        }
        __syncthreads();
        #pragma unroll
        for (int kk = 0; kk < BK; kk++) {
            float a[4], b[4];
            #pragma unroll
            for (int i = 0; i < 4; i++) a[i] = As[ty * 4 + i][kk];
            #pragma unroll
            for (int j = 0; j < 4; j++) b[j] = Bs[kk][tx * 4 + j];
            #pragma unroll
            for (int i = 0; i < 4; i++)
                #pragma unroll
                for (int j = 0; j < 4; j++)
                    acc[i][j] += a[i] * b[j];
        }
        __syncthreads();
    }

    int b = bh / NUM_HEADS, h = bh % NUM_HEADS;
    #pragma unroll
    for (int i = 0; i < 4; i++) {
        int t = row0 + ty * 4 + i;
        size_t obase = ((size_t)(b * T_ + t)) * D_MODEL + h * HEAD_DIM;
        #pragma unroll
        for (int j = 0; j < 4; j++)
            g_ao[obase + tx * 4 + j] = acc[i][j];
    }
}

// ---------------------------------------------------------------------------
// Kernel 5: y = g_ao @ Wo + bo.  M=4096, N=1024, K=1024. Tile 64x64x16.
// ---------------------------------------------------------------------------
__global__ void proj_gemm(const float* __restrict__ Wo,
                          const float* __restrict__ bo,
                          float* __restrict__ y) {
    const int BM = 64, BN = 64, BK = 16;
    __shared__ float As[BM][BK + 1];
    __shared__ float Bs[BK][BN];

    int tid = threadIdx.x;
    int tx = tid & 15, ty = tid >> 4;
    int row0 = blockIdx.y * BM;
    int col0 = blockIdx.x * BN;

    float acc[4][4] = {};
    for (int kt = 0; kt < D_MODEL; kt += BK) {
        #pragma unroll
        for (int i = tid; i < BM * BK; i += 256) {
            int m = i >> 4, kk = i & 15;
            As[m][kk] = g_ao[(size_t)(row0 + m) * D_MODEL + kt + kk];
        }
        #pragma unroll
        for (int i = tid; i < BK * BN; i += 256) {
            int kk = i >> 6, n = i & 63;
            Bs[kk][n] = Wo[(size_t)(kt + kk) * D_MODEL + col0 + n];
        }
        __syncthreads();
        #pragma unroll
        for (int kk = 0; kk < BK; kk++) {
            float a[4], b[4];
            #pragma unroll
            for (int i = 0; i < 4; i++) a[i] = As[ty * 4 + i][kk];
            #pragma unroll
            for (int j = 0; j < 4; j++) b[j] = Bs[kk][tx * 4 + j];
            #pragma unroll
            for (int i = 0; i < 4; i++)
                #pragma unroll
                for (int j = 0; j < 4; j++)
                    acc[i][j] += a[i] * b[j];
        }
        __syncthreads();
    }

    #pragma unroll
    for (int i = 0; i < 4; i++) {
        int r = row0 + ty * 4 + i;
        #pragma unroll
        for (int j = 0; j < 4; j++) {
            int c = col0 + tx * 4 + j;
            y[(size_t)r * D_MODEL + c] = acc[i][j] + bo[c];
        }
    }
}

// ---------------------------------------------------------------------------
extern "C" void kernel_launch(void* const* d_in, const int* in_sizes, int n_in,
                              void* d_out, int out_size) {
    const float* x    = (const float*)d_in[0];
    const float* Wqkv = (const float*)d_in[1];
    const float* bqkv = (const float*)d_in[2];
    const float* Wo   = (const float*)d_in[3];
    const float* bo   = (const float*)d_in[4];

    float* y   = (float*)d_out;                                // [B,T,D]
    float* wts = (float*)d_out + (size_t)BT * D_MODEL;         // [B,H,T,T]

    // 1) QKV projection + scatter to per-head layout
    qkv_gemm<<<dim3(3 * D_MODEL / 64, BT / 64), 256>>>(x, Wqkv, bqkv);

    // 2) raw scores straight into the d_out weights region
    scores_gemm<<<dim3(T_ / 64, T_ / 64, BHEADS), 256>>>(wts);

    // 3) in-place softmax over rows of weights
    softmax_rows<<<BHEADS * T_, 256>>>(wts);

    // 4) attention output = weights @ V  -> [B,T,D] scratch
    av_gemm<<<dim3(1, T_ / 64, BHEADS), 256>>>(wts);

    // 5) output projection
    proj_gemm<<<dim3(D_MODEL / 64, BT / 64), 256>>>(Wo, bo, y);
}

// round 2
// speedup vs baseline: 1.3252x; 1.3252x over previous
#include <cuda_runtime.h>
#include <math.h>
#include <stdint.h>

#define D_MODEL   1024
#define NH        16
#define HD        64
#define B_        2
#define T_        2048
#define BT        4096
#define BH        32

// Scratch (allocation-free rule: __device__ globals)
__device__ float g_q [BH * T_ * HD];   // [bh][t][dd]
__device__ float g_kt[BH * HD * T_];   // [bh][dd][t]  (K pre-transposed)
__device__ float g_v [BH * T_ * HD];   // [bh][t][dd]
__device__ float g_ao[BT * D_MODEL];   // [b*t][D]

// ---------------- f32x2 packed-FMA helpers (Blackwell) ----------------
__device__ __forceinline__ unsigned long long pk2(float lo, float hi) {
    unsigned long long r;
    asm("mov.b64 %0, {%1, %2};" : "=l"(r) : "f"(lo), "f"(hi));
    return r;
}
__device__ __forceinline__ void fma2(unsigned long long& d,
                                     unsigned long long a, unsigned long long b) {
    asm("fma.rn.f32x2 %0, %1, %2, %0;" : "+l"(d) : "l"(a), "l"(b));
}
__device__ __forceinline__ float2 upk(unsigned long long v) {
    float lo, hi;
    asm("mov.b64 {%0, %1}, %2;" : "=f"(lo), "=f"(hi) : "l"(v));
    return make_float2(lo, hi);
}
// ---------------- cp.async helpers ----------------
__device__ __forceinline__ void cpasync16(uint32_t s, const void* g) {
    asm volatile("cp.async.cg.shared.global [%0], [%1], 16;" :: "r"(s), "l"(g));
}
__device__ __forceinline__ void cpcommit() { asm volatile("cp.async.commit_group;"); }
template <int N> __device__ __forceinline__ void cpwait() {
    asm volatile("cp.async.wait_group %0;" :: "n"(N));
}

// ===========================================================================
// Kernel 1: QKV = x @ Wqkv + bqkv.  M=4096, N=3072, K=1024.
// BM=128 BN=128 BK=16, 8x8 microtile, f32x2 inner loop.
// Epilogue scatters: Q,V -> [bh][t][dd];  K -> transposed [bh][dd][t].
// ===========================================================================
__global__ void __launch_bounds__(256) qkv_gemm(const float* __restrict__ X,
                                                const float* __restrict__ W,
                                                const float* __restrict__ bias) {
    __shared__ float As[128][20];
    __shared__ float Bs[16][128];

    int tid = threadIdx.x;
    int tx = tid & 15, ty = tid >> 4;
    int row0 = blockIdx.y * 128, col0 = blockIdx.x * 128;

    unsigned long long acc[8][4];
    #pragma unroll
    for (int i = 0; i < 8; i++)
        #pragma unroll
        for (int j = 0; j < 4; j++) acc[i][j] = 0ULL;

    for (int kt = 0; kt < D_MODEL; kt += 16) {
        #pragma unroll
        for (int p = 0; p < 2; p++) {
            int idx = tid + p * 256;
            int m = idx >> 2, kg = idx & 3;
            *(float4*)&As[m][kg * 4] =
                *(const float4*)&X[(size_t)(row0 + m) * D_MODEL + kt + kg * 4];
            int k = idx >> 5, ng = idx & 31;
            *(float4*)&Bs[k][ng * 4] =
                *(const float4*)&W[(size_t)(kt + k) * (3 * D_MODEL) + col0 + ng * 4];
        }
        __syncthreads();

        #pragma unroll
        for (int k4 = 0; k4 < 4; k4++) {
            float a4f[8][4];
            #pragma unroll
            for (int i = 0; i < 8; i++)
                *(float4*)&a4f[i][0] = *(float4*)&As[ty * 8 + i][k4 * 4];
            #pragma unroll
            for (int kk = 0; kk < 4; kk++) {
                unsigned long long ad[8];
                #pragma unroll
                for (int i = 0; i < 8; i++) ad[i] = pk2(a4f[i][kk], a4f[i][kk]);
                float4 b0 = *(float4*)&Bs[k4 * 4 + kk][tx * 4];
                float4 b1 = *(float4*)&Bs[k4 * 4 + kk][64 + tx * 4];
                unsigned long long b2[4] = {pk2(b0.x, b0.y), pk2(b0.z, b0.w),
                                            pk2(b1.x, b1.y), pk2(b1.z, b1.w)};
                #pragma unroll
                for (int i = 0; i < 8; i++)
                    #pragma unroll
                    for (int j = 0; j < 4; j++) fma2(acc[i][j], ad[i], b2[j]);
            }
        }
        __syncthreads();
    }

    // ---- epilogue: bias + scatter ----
    int which = col0 / D_MODEL;          // uniform per block (128 | 1024)
    int dbase = col0 % D_MODEL;
    float ba[4], bb[4];
    #pragma unroll
    for (int j = 0; j < 4; j++) {
        ba[j] = bias[col0 + tx * 4 + j];
        bb[j] = bias[col0 + 64 + tx * 4 + j];
    }
    int r_ = row0 + ty * 8;
    int b = r_ >> 11, t0 = r_ & 2047;
    int d0 = dbase + tx * 4, d1 = dbase + 64 + tx * 4;
    int h0 = d0 >> 6, dd0 = d0 & 63;
    int h1 = d1 >> 6, dd1 = d1 & 63;
    int bh0 = b * NH + h0, bh1 = b * NH + h1;

    float vals[8][8];
    #pragma unroll
    for (int i = 0; i < 8; i++) {
        float2 p0 = upk(acc[i][0]), p1 = upk(acc[i][1]);
        float2 p2 = upk(acc[i][2]), p3 = upk(acc[i][3]);
        vals[i][0] = p0.x + ba[0]; vals[i][1] = p0.y + ba[1];
        vals[i][2] = p1.x + ba[2]; vals[i][3] = p1.y + ba[3];
        vals[i][4] = p2.x + bb[0]; vals[i][5] = p2.y + bb[1];
        vals[i][6] = p3.x + bb[2]; vals[i][7] = p3.y + bb[3];
    }

    if (which == 1) {
        // K: transposed store -> g_kt[bh][dd][t], t0..t0+7 contiguous
        #pragma unroll
        for (int jj = 0; jj < 4; jj++) {
            float4 lo = make_float4(vals[0][jj], vals[1][jj], vals[2][jj], vals[3][jj]);
            float4 hi = make_float4(vals[4][jj], vals[5][jj], vals[6][jj], vals[7][jj]);
            float* p = &g_kt[((size_t)bh0 * HD + dd0 + jj) * T_ + t0];
            *(float4*)p = lo; *(float4*)(p + 4) = hi;
            float4 lo2 = make_float4(vals[0][4 + jj], vals[1][4 + jj], vals[2][4 + jj], vals[3][4 + jj]);
            float4 hi2 = make_float4(vals[4][4 + jj], vals[5][4 + jj], vals[6][4 + jj], vals[7][4 + jj]);
            float* q = &g_kt[((size_t)bh1 * HD + dd1 + jj) * T_ + t0];
            *(float4*)q = lo2; *(float4*)(q + 4) = hi2;
        }
    } else {
        float* dst = (which == 0) ? g_q : g_v;
        #pragma unroll
        for (int i = 0; i < 8; i++) {
            int t = t0 + i;
            *(float4*)&dst[((size_t)bh0 * T_ + t) * HD + dd0] =
                make_float4(vals[i][0], vals[i][1], vals[i][2], vals[i][3]);
            *(float4*)&dst[((size_t)bh1 * T_ + t) * HD + dd1] =
                make_float4(vals[i][4], vals[i][5], vals[i][6], vals[i][7]);
        }
    }
}

// ===========================================================================
// Kernel 2: fused scores + softmax.  One block = 16 query rows x all 2048 keys
// of one head. Scores live entirely in registers (128 floats/thread).
// K chunks (256 keys x 64 dims) double-buffered in smem via cp.async.
// Writes normalized weights straight into d_out.
// ===========================================================================
#define SC_SMEM_FLOATS (16 * 68 + 2 * 64 * 264)

__global__ void __launch_bounds__(256, 1) attn_scores(float* __restrict__ wts) {
    extern __shared__ float sm[];
    float* Qs  = sm;              // [16][68]
    float* Kts = sm + 16 * 68;    // [2][64][264]

    int tid = threadIdx.x;
    int tx = tid & 31, ty = tid >> 5;    // warp = ty; rows {ty, ty+8}
    int bh = blockIdx.y;
    int r0 = blockIdx.x * 16;

    const float* qh  = g_q  + (size_t)bh * T_ * HD;
    const float* kth = g_kt + (size_t)bh * HD * T_;

    {   // load Q tile [16][64]
        int r = tid >> 4, dg = tid & 15;
        *(float4*)&Qs[r * 68 + dg * 4] =
            *(const float4*)&qh[(size_t)(r0 + r) * HD + dg * 4];
    }

    unsigned long long sc[2][32];
    #pragma unroll
    for (int rr = 0; rr < 2; rr++)
        #pragma unroll
        for (int u = 0; u < 32; u++) sc[rr][u] = 0ULL;

    // prefetch chunk 0
    #pragma unroll
    for (int p = 0; p < 16; p++) {
        int idx = tid + p * 256;
        int k = idx >> 6, kg = idx & 63;
        uint32_t dst = (uint32_t)__cvta_generic_to_shared(&Kts[(size_t)k * 264 + kg * 4]);
        cpasync16(dst, &kth[(size_t)k * T_ + kg * 4]);
    }
    cpcommit();
    __syncthreads();   // Qs visible

    #pragma unroll
    for (int c = 0; c < 8; c++) {
        if (c < 7) {
            int buf = (c + 1) & 1;
            #pragma unroll
            for (int p = 0; p < 16; p++) {
                int idx = tid + p * 256;
                int k = idx >> 6, kg = idx & 63;
                uint32_t dst = (uint32_t)__cvta_generic_to_shared(
                    &Kts[((size_t)buf * 64 + k) * 264 + kg * 4]);
                cpasync16(dst, &kth[(size_t)k * T_ + (c + 1) * 256 + kg * 4]);
            }
            cpcommit();
            cpwait<1>();
        } else {
            cpwait<0>();
        }
        __syncthreads();

        const float* Kb = &Kts[(size_t)(c & 1) * 64 * 264];
        const float* Q0 = &Qs[ty * 68];
        const float* Q1 = &Qs[(ty + 8) * 68];

        #pragma unroll 4
        for (int k = 0; k < 64; k++) {
            float q0 = Q0[k], q1 = Q1[k];
            unsigned long long ad0 = pk2(q0, q0), ad1 = pk2(q1, q1);
            float4 v0 = *(const float4*)&Kb[k * 264 + tx * 4];
            float4 v1 = *(const float4*)&Kb[k * 264 + 128 + tx * 4];
            unsigned long long b0 = pk2(v0.x, v0.y), b1 = pk2(v0.z, v0.w);
            unsigned long long b2 = pk2(v1.x, v1.y), b3 = pk2(v1.z, v1.w);
            fma2(sc[0][c * 4 + 0], ad0, b0); fma2(sc[0][c * 4 + 1], ad0, b1);
            fma2(sc[0][c * 4 + 2], ad0, b2); fma2(sc[0][c * 4 + 3], ad0, b3);
            fma2(sc[1][c * 4 + 0], ad1, b0); fma2(sc[1][c * 4 + 1], ad1, b1);
            fma2(sc[1][c * 4 + 2], ad1, b2); fma2(sc[1][c * 4 + 3], ad1, b3);
        }
        __syncthreads();   // safe to overwrite the other buffer next iter
    }

    // ---- softmax over each owned row (warp-wide) + write weights ----
    const float SCALE = 0.125f;   // 1/sqrt(64)
    #pragma unroll
    for (int rr = 0; rr < 2; rr++) {
        int r = r0 + ty + rr * 8;
        float m = -1e30f;
        #pragma unroll
        for (int u = 0; u < 32; u++) {
            float2 p = upk(sc[rr][u]);
            m = fmaxf(m, fmaxf(p.x, p.y));
        }
        #pragma unroll
        for (int o = 16; o > 0; o >>= 1)
            m = fmaxf(m, __shfl_xor_sync(0xffffffffu, m, o));

        float s = 0.f;
        float vbuf[64];
        #pragma unroll
        for (int u = 0; u < 32; u++) {
            float2 p = upk(sc[rr][u]);
            float e0 = __expf((p.x - m) * SCALE);
            float e1 = __expf((p.y - m) * SCALE);
            vbuf[u * 2] = e0; vbuf[u * 2 + 1] = e1;
            s += e0 + e1;
        }
        #pragma unroll
        for (int o = 16; o > 0; o >>= 1)
            s += __shfl_xor_sync(0xffffffffu, s, o);
        float inv = 1.f / s;

        float* wr = wts + ((size_t)bh * T_ + r) * T_;
        #pragma unroll
        for (int c = 0; c < 8; c++) {
            float4 w0 = make_float4(vbuf[c * 8 + 0] * inv, vbuf[c * 8 + 1] * inv,
                                    vbuf[c * 8 + 2] * inv, vbuf[c * 8 + 3] * inv);
            float4 w1 = make_float4(vbuf[c * 8 + 4] * inv, vbuf[c * 8 + 5] * inv,
                                    vbuf[c * 8 + 6] * inv, vbuf[c * 8 + 7] * inv);
            *(float4*)&wr[c * 256 + tx * 4] = w0;
            *(float4*)&wr[c * 256 + 128 + tx * 4] = w1;
        }
    }
}

// ===========================================================================
// Kernel 3: attention-out = weights @ V.  Per head: M=2048, N=64, K=2048.
// BM=128 BN=64 BK=32, 8x4 microtile (row-paired f32x2).
// ===========================================================================
__global__ void __launch_bounds__(256) av_gemm(const float* __restrict__ wts) {
    __shared__ float Ws[128][36];
    __shared__ float Vs[32][64];

    int tid = threadIdx.x;
    int tx = tid & 15, ty = tid >> 4;
    int bh = blockIdx.y;
    int r0 = blockIdx.x * 128;

    const float* wrow = wts + (size_t)bh * T_ * T_;
    const float* vh   = g_v + (size_t)bh * T_ * HD;

    unsigned long long acc[4][4];   // [rowpair][col]
    #pragma unroll
    for (int i = 0; i < 4; i++)
        #pragma unroll
        for (int j = 0; j < 4; j++) acc[i][j] = 0ULL;

    for (int kt = 0; kt < T_; kt += 32) {
        #pragma unroll
        for (int p = 0; p < 4; p++) {
            int idx = tid + p * 256;
            int m = idx >> 3, kg = idx & 7;
            *(float4*)&Ws[m][kg * 4] =
                *(const float4*)&wrow[(size_t)(r0 + m) * T_ + kt + kg * 4];
        }
        #pragma unroll
        for (int p = 0; p < 2; p++) {
            int idx = tid + p * 256;
            int k = idx >> 4, ng = idx & 15;
            *(float4*)&Vs[k][ng * 4] =
                *(const float4*)&vh[(size_t)(kt + k) * HD + ng * 4];
        }
        __syncthreads();

        #pragma unroll
        for (int k4 = 0; k4 < 8; k4++) {
            float a4f[8][4];
            #pragma unroll
            for (int i = 0; i < 8; i++)
                *(float4*)&a4f[i][0] = *(float4*)&Ws[ty * 8 + i][k4 * 4];
            #pragma unroll
            for (int kk = 0; kk < 4; kk++) {
                unsigned long long a2[4];
                #pragma unroll
                for (int i2 = 0; i2 < 4; i2++)
                    a2[i2] = pk2(a4f[2 * i2][kk], a4f[2 * i2 + 1][kk]);
                float4 bv = *(float4*)&Vs[k4 * 4 + kk][tx * 4];
                unsigned long long bd[4] = {pk2(bv.x, bv.x), pk2(bv.y, bv.y),
                                            pk2(bv.z, bv.z), pk2(bv.w, bv.w)};
                #pragma unroll
                for (int i2 = 0; i2 < 4; i2++)
                    #pragma unroll
                    for (int j = 0; j < 4; j++) fma2(acc[i2][j], a2[i2], bd[j]);
            }
        }
        __syncthreads();
    }

    int b = bh >> 4, h = bh & 15;
    #pragma unroll
    for (int i2 = 0; i2 < 4; i2++) {
        float2 c0 = upk(acc[i2][0]), c1 = upk(acc[i2][1]);
        float2 c2 = upk(acc[i2][2]), c3 = upk(acc[i2][3]);
        int t = r0 + ty * 8 + 2 * i2;
        *(float4*)&g_ao[((size_t)(b * T_ + t)) * D_MODEL + h * HD + tx * 4] =
            make_float4(c0.x, c1.x, c2.x, c3.x);
        *(float4*)&g_ao[((size_t)(b * T_ + t + 1)) * D_MODEL + h * HD + tx * 4] =
            make_float4(c0.y, c1.y, c2.y, c3.y);
    }
}

// ===========================================================================
// Kernel 4: y = g_ao @ Wo + bo.  M=4096, N=1024, K=1024. Same tiling as qkv.
// ===========================================================================
__global__ void __launch_bounds__(256) proj_gemm(const float* __restrict__ Wo,
                                                 const float* __restrict__ bo,
                                                 float* __restrict__ y) {
    __shared__ float As[128][20];
    __shared__ float Bs[16][128];

    int tid = threadIdx.x;
    int tx = tid & 15, ty = tid >> 4;
    int row0 = blockIdx.y * 128, col0 = blockIdx.x * 128;

    unsigned long long acc[8][4];
    #pragma unroll
    for (int i = 0; i < 8; i++)
        #pragma unroll
        for (int j = 0; j < 4; j++) acc[i][j] = 0ULL;

    for (int kt = 0; kt < D_MODEL; kt += 16) {
        #pragma unroll
        for (int p = 0; p < 2; p++) {
            int idx = tid + p * 256;
            int m = idx >> 2, kg = idx & 3;
            *(float4*)&As[m][kg * 4] =
                *(const float4*)&g_ao[(size_t)(row0 + m) * D_MODEL + kt + kg * 4];
            int k = idx >> 5, ng = idx & 31;
            *(float4*)&Bs[k][ng * 4] =
                *(const float4*)&Wo[(size_t)(kt + k) * D_MODEL + col0 + ng * 4];
        }
        __syncthreads();

        #pragma unroll
        for (int k4 = 0; k4 < 4; k4++) {
            float a4f[8][4];
            #pragma unroll
            for (int i = 0; i < 8; i++)
                *(float4*)&a4f[i][0] = *(float4*)&As[ty * 8 + i][k4 * 4];
            #pragma unroll
            for (int kk = 0; kk < 4; kk++) {
                unsigned long long ad[8];
                #pragma unroll
                for (int i = 0; i < 8; i++) ad[i] = pk2(a4f[i][kk], a4f[i][kk]);
                float4 b0 = *(float4*)&Bs[k4 * 4 + kk][tx * 4];
                float4 b1 = *(float4*)&Bs[k4 * 4 + kk][64 + tx * 4];
                unsigned long long b2[4] = {pk2(b0.x, b0.y), pk2(b0.z, b0.w),
                                            pk2(b1.x, b1.y), pk2(b1.z, b1.w)};
                #pragma unroll
                for (int i = 0; i < 8; i++)
                    #pragma unroll
                    for (int j = 0; j < 4; j++) fma2(acc[i][j], ad[i], b2[j]);
            }
        }
        __syncthreads();
    }

    int r = row0 + ty * 8;
    #pragma unroll
    for (int i = 0; i < 8; i++) {
        float2 p0 = upk(acc[i][0]), p1 = upk(acc[i][1]);
        float2 p2 = upk(acc[i][2]), p3 = upk(acc[i][3]);
        int c0 = col0 + tx * 4, c1 = col0 + 64 + tx * 4;
        *(float4*)&y[(size_t)(r + i) * D_MODEL + c0] =
            make_float4(p0.x + bo[c0], p0.y + bo[c0 + 1], p1.x + bo[c0 + 2], p1.y + bo[c0 + 3]);
        *(float4*)&y[(size_t)(r + i) * D_MODEL + c1] =
            make_float4(p2.x + bo[c1], p2.y + bo[c1 + 1], p3.x + bo[c1 + 2], p3.y + bo[c1 + 3]);
    }
}

// ===========================================================================
extern "C" void kernel_launch(void* const* d_in, const int* in_sizes, int n_in,
                              void* d_out, int out_size) {
    const float* x    = (const float*)d_in[0];
    const float* Wqkv = (const float*)d_in[1];
    const float* bqkv = (const float*)d_in[2];
    const float* Wo   = (const float*)d_in[3];
    const float* bo   = (const float*)d_in[4];

    float* y   = (float*)d_out;                         // [B,T,D]
    float* wts = (float*)d_out + (size_t)BT * D_MODEL;  // [B,H,T,T]

    cudaFuncSetAttribute(attn_scores, cudaFuncAttributeMaxDynamicSharedMemorySize,
                         SC_SMEM_FLOATS * 4);

    qkv_gemm<<<dim3(24, 32), 256>>>(x, Wqkv, bqkv);
    attn_scores<<<dim3(128, 32), 256, SC_SMEM_FLOATS * 4>>>(wts);
    av_gemm<<<dim3(16, 32), 256>>>(wts);
    proj_gemm<<<dim3(8, 32), 256>>>(Wo, bo, y);
}

// round 5
// speedup vs baseline: 3.1857x; 2.4039x over previous
#include <cuda_runtime.h>
#include <math.h>
#include <stdint.h>

#define D_MODEL 1024
#define NH      16
#define HD      64
#define B_      2
#define T_      2048
#define BT      4096
#define BH      32

// ------------------------- device scratch (no allocs) ----------------------
__device__ float g_q  [BH * T_ * HD];      // [bh][t][dd]
__device__ float g_k  [BH * T_ * HD];      // [bh][s][dd]
__device__ float g_v  [BH * T_ * HD];      // [bh][t][dd]
__device__ float g_vt [BH * HD * T_];      // [bh][dd][t]
__device__ float g_ao [BT * D_MODEL];      // [b*t][D]
__device__ float g_wt [3 * D_MODEL * D_MODEL];   // Wqkv^T [3072][1024]
__device__ float g_wot[D_MODEL * D_MODEL];       // Wo^T   [1024][1024]
__device__ float g_rowsum[BH * T_];

// ------------------------------ helpers ------------------------------------
__device__ __forceinline__ uint32_t s2u(const void* p) {
    return (uint32_t)__cvta_generic_to_shared(p);
}
__device__ __forceinline__ void cpa16(uint32_t d, const void* g) {
    asm volatile("cp.async.cg.shared.global [%0], [%1], 16;" :: "r"(d), "l"(g));
}
__device__ __forceinline__ void cpcommit() { asm volatile("cp.async.commit_group;"); }
template <int N> __device__ __forceinline__ void cpwait() {
    asm volatile("cp.async.wait_group %0;" :: "n"(N));
}
__device__ __forceinline__ uint32_t f2tf(float f) {
    uint32_t r; asm("cvt.rna.tf32.f32 %0, %1;" : "=r"(r) : "f"(f)); return r;
}
// m16n8k8 tf32 mma, fp32 accumulate
__device__ __forceinline__ void mma8(float* c, const uint32_t* a, const uint32_t* b) {
    asm volatile("mma.sync.aligned.m16n8k8.row.col.f32.tf32.tf32.f32 "
        "{%0,%1,%2,%3}, {%4,%5,%6,%7}, {%8,%9}, {%0,%1,%2,%3};"
        : "+f"(c[0]), "+f"(c[1]), "+f"(c[2]), "+f"(c[3])
        : "r"(a[0]), "r"(a[1]), "r"(a[2]), "r"(a[3]), "r"(b[0]), "r"(b[1]));
}

// ======================= prep kernels =======================================
__global__ void zero_rowsum() {
    g_rowsum[blockIdx.x * 256 + threadIdx.x] = 0.f;
}

__global__ void transpose_w(const float* __restrict__ in, float* __restrict__ out,
                            int R, int C) {   // in[R][C] -> out[C][R]
    __shared__ float tb[32][33];
    int bx = blockIdx.x * 32, by = blockIdx.y * 32;
    int x = bx + threadIdx.x;
    #pragma unroll
    for (int i = threadIdx.y; i < 32; i += 8)
        tb[i][threadIdx.x] = in[(size_t)(by + i) * C + x];
    __syncthreads();
    int x2 = by + threadIdx.x;
    #pragma unroll
    for (int i = threadIdx.y; i < 32; i += 8)
        out[(size_t)(bx + i) * R + x2] = tb[threadIdx.x][i];
}

__global__ void transpose_v() {   // g_v [bh][2048][64] -> g_vt [bh][64][2048]
    __shared__ float tb[32][33];
    int bh = blockIdx.z;
    const float* in = g_v + (size_t)bh * T_ * HD;
    float* out = g_vt + (size_t)bh * HD * T_;
    int bx = blockIdx.x * 32, by = blockIdx.y * 32;
    int x = bx + threadIdx.x;
    #pragma unroll
    for (int i = threadIdx.y; i < 32; i += 8)
        tb[i][threadIdx.x] = in[(size_t)(by + i) * HD + x];
    __syncthreads();
    int x2 = by + threadIdx.x;
    #pragma unroll
    for (int i = threadIdx.y; i < 32; i += 8)
        out[(size_t)(bx + i) * T_ + x2] = tb[threadIdx.x][i];
}

// ======================= big projection GEMM ================================
// C[M=4096][N] = A[M][1024] @ Bt[N][1024]^T, tile 128x128, BK=16, 2-stage.
// 8 warps as 4(m) x 2(n): warp tile 32x64.
// MODE 0: qkv (scatter epilogue). MODE 1: proj (bias -> y).
template <int MODE>
__global__ void __launch_bounds__(256, 1)
gemm_big(const float* __restrict__ A, const float* __restrict__ Bt,
         const float* __restrict__ bias, float* __restrict__ Cout) {
    __shared__ float As[2][128][20];
    __shared__ float Bs[2][128][20];

    int tid = threadIdx.x, wid = tid >> 5, lane = tid & 31;
    int gr = lane >> 2, tq = lane & 3;
    int warpm = wid & 3, warpn = wid >> 2;
    int row0 = blockIdx.y * 128, col0 = blockIdx.x * 128;

    float acc[2][8][4];
    #pragma unroll
    for (int i = 0; i < 2; i++)
        #pragma unroll
        for (int j = 0; j < 8; j++)
            #pragma unroll
            for (int q = 0; q < 4; q++) acc[i][j][q] = 0.f;

    auto load_stage = [&](int c, int s) {
        #pragma unroll
        for (int p = 0; p < 2; p++) {
            int idx = tid + p * 256;
            int r = idx >> 2, c4 = idx & 3;
            cpa16(s2u(&As[s][r][c4 * 4]), &A[(size_t)(row0 + r) * 1024 + c * 16 + c4 * 4]);
            cpa16(s2u(&Bs[s][r][c4 * 4]), &Bt[(size_t)(col0 + r) * 1024 + c * 16 + c4 * 4]);
        }
        cpcommit();
    };

    load_stage(0, 0);
    load_stage(1, 1);

    for (int c = 0; c < 64; c++) {
        int s = c & 1;
        if (c < 63) cpwait<1>(); else cpwait<0>();
        __syncthreads();

        #pragma unroll
        for (int k8 = 0; k8 < 16; k8 += 8) {
            uint32_t a[2][4];
            #pragma unroll
            for (int i = 0; i < 2; i++) {
                int r = warpm * 32 + i * 16 + gr;
                int cc = k8 + tq;
                a[i][0] = f2tf(As[s][r][cc]);     a[i][1] = f2tf(As[s][r + 8][cc]);
                a[i][2] = f2tf(As[s][r][cc + 4]); a[i][3] = f2tf(As[s][r + 8][cc + 4]);
            }
            #pragma unroll
            for (int j = 0; j < 8; j++) {
                int nb = warpn * 64 + j * 8 + gr;
                uint32_t b[2];
                b[0] = f2tf(Bs[s][nb][k8 + tq]);
                b[1] = f2tf(Bs[s][nb][k8 + 4 + tq]);
                mma8(acc[0][j], a[0], b);
                mma8(acc[1][j], a[1], b);
            }
        }
        __syncthreads();
        if (c + 2 < 64) load_stage(c + 2, s);
    }

    // ---- epilogue ----
    #pragma unroll
    for (int i = 0; i < 2; i++) {
        #pragma unroll
        for (int half = 0; half < 2; half++) {
            int m = row0 + warpm * 32 + i * 16 + gr + half * 8;
            #pragma unroll
            for (int j = 0; j < 8; j++) {
                int col = col0 + warpn * 64 + j * 8 + 2 * tq;
                float v0 = acc[i][j][half * 2 + 0] + __ldg(&bias[col]);
                float v1 = acc[i][j][half * 2 + 1] + __ldg(&bias[col + 1]);
                if (MODE == 1) {
                    *(float2*)&Cout[(size_t)m * 1024 + col] = make_float2(v0, v1);
                } else {
                    int which = col >> 10;
                    int d = col & 1023, h = d >> 6, dd = d & 63;
                    int b = m >> 11, t = m & 2047;
                    float* dst = (which == 0) ? g_q : (which == 1) ? g_k : g_v;
                    *(float2*)&dst[((size_t)(b * NH + h) * T_ + t) * HD + dd] =
                        make_float2(v0, v1);
                }
            }
        }
    }
}

// ======================= scores + exp + rowsum ==============================
// Tile 128 q x 128 s, K=64 single shot. E = exp(score/8) -> wts; rowsums atomic.
__global__ void __launch_bounds__(256, 1) attn_scores(float* __restrict__ wts) {
    extern __shared__ float sm[];
    float* Qs = sm;               // [128][68]
    float* Ks = sm + 128 * 68;    // [128][68]

    int tid = threadIdx.x, wid = tid >> 5, lane = tid & 31;
    int gr = lane >> 2, tq = lane & 3;
    int warpm = wid & 3, warpn = wid >> 2;
    int s0 = blockIdx.x * 128, r0 = blockIdx.y * 128, bh = blockIdx.z;

    const float* qh = g_q + ((size_t)bh * T_ + r0) * HD;
    const float* kh = g_k + ((size_t)bh * T_ + s0) * HD;
    #pragma unroll
    for (int p = 0; p < 8; p++) {
        int idx = tid + p * 256;
        int r = idx >> 4, c4 = idx & 15;
        cpa16(s2u(&Qs[r * 68 + c4 * 4]), qh + (size_t)r * HD + c4 * 4);
        cpa16(s2u(&Ks[r * 68 + c4 * 4]), kh + (size_t)r * HD + c4 * 4);
    }
    cpcommit(); cpwait<0>();
    __syncthreads();

    float acc[2][8][4];
    #pragma unroll
    for (int i = 0; i < 2; i++)
        #pragma unroll
        for (int j = 0; j < 8; j++)
            #pragma unroll
            for (int q = 0; q < 4; q++) acc[i][j][q] = 0.f;

    #pragma unroll
    for (int k8 = 0; k8 < 64; k8 += 8) {
        uint32_t a[2][4];
        #pragma unroll
        for (int i = 0; i < 2; i++) {
            int r = warpm * 32 + i * 16 + gr;
            int cc = k8 + tq;
            a[i][0] = f2tf(Qs[r * 68 + cc]);       a[i][1] = f2tf(Qs[(r + 8) * 68 + cc]);
            a[i][2] = f2tf(Qs[r * 68 + cc + 4]);   a[i][3] = f2tf(Qs[(r + 8) * 68 + cc + 4]);
        }
        #pragma unroll
        for (int j = 0; j < 8; j++) {
            int nb = warpn * 64 + j * 8 + gr;
            uint32_t b[2];
            b[0] = f2tf(Ks[nb * 68 + k8 + tq]);
            b[1] = f2tf(Ks[nb * 68 + k8 + 4 + tq]);
            mma8(acc[0][j], a[0], b);
            mma8(acc[1][j], a[1], b);
        }
    }

    // exp + store + rowsum
    #pragma unroll
    for (int i = 0; i < 2; i++) {
        #pragma unroll
        for (int half = 0; half < 2; half++) {
            int r = r0 + warpm * 32 + i * 16 + gr + half * 8;
            float sum = 0.f;
            float* wr = wts + ((size_t)bh * T_ + r) * T_;
            #pragma unroll
            for (int j = 0; j < 8; j++) {
                int col = s0 + warpn * 64 + j * 8 + 2 * tq;
                float e0 = __expf(0.125f * acc[i][j][half * 2 + 0]);
                float e1 = __expf(0.125f * acc[i][j][half * 2 + 1]);
                sum += e0 + e1;
                *(float2*)&wr[col] = make_float2(e0, e1);
            }
            // reduce over the 4 lanes of this row-group (tq = 0..3)
            sum += __shfl_xor_sync(0xffffffffu, sum, 1);
            sum += __shfl_xor_sync(0xffffffffu, sum, 2);
            if (tq == 0) atomicAdd(&g_rowsum[(size_t)bh * T_ + r], sum);
        }
    }
}

// ======================= AV GEMM (normalize + writeback) ====================
// Tile 128 t x 64 dd, K=2048 (128 BK=16 stages). 8 warps 4x2: warp 32x32.
// E loaded by LDG, scaled by 1/rowsum, stored to smem + written back to wts.
__global__ void __launch_bounds__(256, 1) av_gemm(float* __restrict__ wts) {
    __shared__ float Es[2][128][20];
    __shared__ float Vs[2][64][20];
    __shared__ float inv[128];

    int tid = threadIdx.x, wid = tid >> 5, lane = tid & 31;
    int gr = lane >> 2, tq = lane & 3;
    int warpm = wid & 3, warpn = wid >> 2;
    int r0 = blockIdx.x * 128, bh = blockIdx.y;

    if (tid < 128) inv[tid] = 1.f / g_rowsum[(size_t)bh * T_ + r0 + tid];
    __syncthreads();

    float* wb = wts + ((size_t)bh * T_ + r0) * T_;
    const float* vtb = g_vt + (size_t)bh * HD * T_;

    auto stageA = [&](int c, int s) {
        #pragma unroll
        for (int p = 0; p < 2; p++) {
            int idx = tid + p * 256;
            int r = idx >> 2, c4 = idx & 3;
            float4 w = *(const float4*)&wb[(size_t)r * T_ + c * 16 + c4 * 4];
            float iv = inv[r];
            w.x *= iv; w.y *= iv; w.z *= iv; w.w *= iv;
            *(float4*)&Es[s][r][c4 * 4] = w;
            *(float4*)&wb[(size_t)r * T_ + c * 16 + c4 * 4] = w;
        }
    };
    auto stageB = [&](int c, int s) {
        int r = tid >> 2, c4 = tid & 3;
        cpa16(s2u(&Vs[s][r][c4 * 4]), vtb + (size_t)r * T_ + c * 16 + c4 * 4);
        cpcommit();
    };

    float acc[2][4][4];
    #pragma unroll
    for (int i = 0; i < 2; i++)
        #pragma unroll
        for (int j = 0; j < 4; j++)
            #pragma unroll
            for (int q = 0; q < 4; q++) acc[i][j][q] = 0.f;

    stageA(0, 0); stageB(0, 0);
    stageA(1, 1); stageB(1, 1);

    for (int c = 0; c < 128; c++) {
        int s = c & 1;
        if (c < 127) cpwait<1>(); else cpwait<0>();
        __syncthreads();

        #pragma unroll
        for (int k8 = 0; k8 < 16; k8 += 8) {
            uint32_t a[2][4];
            #pragma unroll
            for (int i = 0; i < 2; i++) {
                int r = warpm * 32 + i * 16 + gr;
                int cc = k8 + tq;
                a[i][0] = f2tf(Es[s][r][cc]);     a[i][1] = f2tf(Es[s][r + 8][cc]);
                a[i][2] = f2tf(Es[s][r][cc + 4]); a[i][3] = f2tf(Es[s][r + 8][cc + 4]);
            }
            #pragma unroll
            for (int j = 0; j < 4; j++) {
                int nb = warpn * 32 + j * 8 + gr;
                uint32_t b[2];
                b[0] = f2tf(Vs[s][nb][k8 + tq]);
                b[1] = f2tf(Vs[s][nb][k8 + 4 + tq]);
                mma8(acc[0][j], a[0], b);
                mma8(acc[1][j], a[1], b);
            }
        }
        __syncthreads();
        if (c + 2 < 128) { stageA(c + 2, s); stageB(c + 2, s); }
    }

    int b = bh >> 4, h = bh & 15;
    #pragma unroll
    for (int i = 0; i < 2; i++) {
        #pragma unroll
        for (int half = 0; half < 2; half++) {
            int t = r0 + warpm * 32 + i * 16 + gr + half * 8;
            float* orow = g_ao + (size_t)(b * T_ + t) * D_MODEL + h * HD;
            #pragma unroll
            for (int j = 0; j < 4; j++) {
                int dd = warpn * 32 + j * 8 + 2 * tq;
                *(float2*)&orow[dd] =
                    make_float2(acc[i][j][half * 2 + 0], acc[i][j][half * 2 + 1]);
            }
        }
    }
}

// ===========================================================================
extern "C" void kernel_launch(void* const* d_in, const int* in_sizes, int n_in,
                              void* d_out, int out_size) {
    const float* x    = (const float*)d_in[0];
    const float* Wqkv = (const float*)d_in[1];
    const float* bqkv = (const float*)d_in[2];
    const float* Wo   = (const float*)d_in[3];
    const float* bo   = (const float*)d_in[4];

    float* y   = (float*)d_out;                         // [B,T,D]
    float* wts = (float*)d_out + (size_t)BT * D_MODEL;  // [B,H,T,T]

    const int SC_SMEM = 2 * 128 * 68 * 4;  // 69632 B
    cudaFuncSetAttribute(attn_scores, cudaFuncAttributeMaxDynamicSharedMemorySize, SC_SMEM);

    float *wt_p = nullptr, *wot_p = nullptr, *ao_p = nullptr;
    cudaGetSymbolAddress((void**)&wt_p,  g_wt);
    cudaGetSymbolAddress((void**)&wot_p, g_wot);
    cudaGetSymbolAddress((void**)&ao_p,  g_ao);

    zero_rowsum<<<BH * T_ / 256, 256>>>();
    transpose_w<<<dim3(96, 32), dim3(32, 8)>>>(Wqkv, wt_p, 1024, 3072);
    transpose_w<<<dim3(32, 32), dim3(32, 8)>>>(Wo, wot_p, 1024, 1024);

    // QKV: M=4096, N=3072  -> q, k, v
    gemm_big<0><<<dim3(24, 32), 256>>>(x, wt_p, bqkv, nullptr);
    transpose_v<<<dim3(2, 64, 32), dim3(32, 8)>>>();

    // E = exp(scores/8) into weights region + rowsums
    attn_scores<<<dim3(16, 16, 32), 256, SC_SMEM>>>(wts);

    // AV with normalization; writes final weights back
    av_gemm<<<dim3(16, 32), 256>>>(wts);

    // output projection: M=4096, N=1024
    gemm_big<1><<<dim3(8, 32), 256>>>(ao_p, wot_p, bo, y);
}

// round 6
// speedup vs baseline: 3.7878x; 1.1890x over previous
#include <cuda_runtime.h>
#include <math.h>
#include <stdint.h>

#define D_MODEL 1024
#define NH      16
#define HD      64
#define B_      2
#define T_      2048
#define BT      4096
#define BH      32

// ------------------------- device scratch (no allocs) ----------------------
__device__ float g_x  [BT * D_MODEL];      // x, tf32-rounded
__device__ float g_q  [BH * T_ * HD];      // [bh][t][dd]   (tf32)
__device__ float g_k  [BH * T_ * HD];      // [bh][s][dd]   (tf32)
__device__ float g_v  [BH * T_ * HD];      // [bh][t][dd]   (exact)
__device__ float g_vt [BH * HD * T_];      // [bh][dd][t]   (tf32)
__device__ float g_ao [BT * D_MODEL];      // [b*t][D]      (tf32)
__device__ float g_wt [3 * D_MODEL * D_MODEL];   // Wqkv^T (tf32)
__device__ float g_wot[D_MODEL * D_MODEL];       // Wo^T   (tf32)
__device__ float g_rowsum[BH * T_];

// ------------------------------ helpers ------------------------------------
__device__ __forceinline__ uint32_t s2u(const void* p) {
    return (uint32_t)__cvta_generic_to_shared(p);
}
__device__ __forceinline__ void cpa16(uint32_t d, const void* g) {
    asm volatile("cp.async.cg.shared.global [%0], [%1], 16;" :: "r"(d), "l"(g));
}
__device__ __forceinline__ void cpcommit() { asm volatile("cp.async.commit_group;"); }
template <int N> __device__ __forceinline__ void cpwait() {
    asm volatile("cp.async.wait_group %0;" :: "n"(N));
}
__device__ __forceinline__ float f2tf(float f) {
    uint32_t r; asm("cvt.rna.tf32.f32 %0, %1;" : "=r"(r) : "f"(f));
    return __uint_as_float(r);
}
// m16n8k8 tf32 mma, fp32 accumulate (operands pre-rounded)
__device__ __forceinline__ void mma8(float* c, const uint32_t* a, const uint32_t* b) {
    asm volatile("mma.sync.aligned.m16n8k8.row.col.f32.tf32.tf32.f32 "
        "{%0,%1,%2,%3}, {%4,%5,%6,%7}, {%8,%9}, {%0,%1,%2,%3};"
        : "+f"(c[0]), "+f"(c[1]), "+f"(c[2]), "+f"(c[3])
        : "r"(a[0]), "r"(a[1]), "r"(a[2]), "r"(a[3]), "r"(b[0]), "r"(b[1]));
}

// ======================= prep kernels =======================================
__global__ void zero_rowsum() {
    g_rowsum[blockIdx.x * 256 + threadIdx.x] = 0.f;
}

__global__ void cvt_x(const float* __restrict__ x) {
    size_t i = ((size_t)blockIdx.x * 256 + threadIdx.x) * 4;
    float4 v = *(const float4*)&x[i];
    v.x = f2tf(v.x); v.y = f2tf(v.y); v.z = f2tf(v.z); v.w = f2tf(v.w);
    *(float4*)&g_x[i] = v;
}

__global__ void transpose_w(const float* __restrict__ in, float* __restrict__ out,
                            int R, int C) {   // in[R][C] -> out[C][R], tf32-rounded
    __shared__ float tb[32][33];
    int bx = blockIdx.x * 32, by = blockIdx.y * 32;
    int x = bx + threadIdx.x;
    #pragma unroll
    for (int i = threadIdx.y; i < 32; i += 8)
        tb[i][threadIdx.x] = in[(size_t)(by + i) * C + x];
    __syncthreads();
    int x2 = by + threadIdx.x;
    #pragma unroll
    for (int i = threadIdx.y; i < 32; i += 8)
        out[(size_t)(bx + i) * R + x2] = f2tf(tb[threadIdx.x][i]);
}

__global__ void transpose_v() {   // g_v -> g_vt (tf32)
    __shared__ float tb[32][33];
    int bh = blockIdx.z;
    const float* in = g_v + (size_t)bh * T_ * HD;
    float* out = g_vt + (size_t)bh * HD * T_;
    int bx = blockIdx.x * 32, by = blockIdx.y * 32;
    int x = bx + threadIdx.x;
    #pragma unroll
    for (int i = threadIdx.y; i < 32; i += 8)
        tb[i][threadIdx.x] = in[(size_t)(by + i) * HD + x];
    __syncthreads();
    int x2 = by + threadIdx.x;
    #pragma unroll
    for (int i = threadIdx.y; i < 32; i += 8)
        out[(size_t)(bx + i) * T_ + x2] = f2tf(tb[threadIdx.x][i]);
}

// ======================= big projection GEMM ================================
// C[4096][N] = A[4096][1024] @ Bt[N][1024]^T. Tile 128x128, BK=16, 3 stages,
// one __syncthreads per k-iter. Operands pre-rounded tf32.
#define GBS 20
template <int MODE>
__global__ void __launch_bounds__(256, 2)
gemm_big(const float* __restrict__ A, const float* __restrict__ Bt,
         const float* __restrict__ bias, float* __restrict__ Cout) {
    extern __shared__ float sm[];
    float (*As)[128][GBS] = (float(*)[128][GBS])sm;
    float (*Bs)[128][GBS] = (float(*)[128][GBS])(sm + 3 * 128 * GBS);

    int tid = threadIdx.x, wid = tid >> 5, lane = tid & 31;
    int gr = lane >> 2, tq = lane & 3;
    int warpm = wid & 3, warpn = wid >> 2;
    int row0 = blockIdx.y * 128, col0 = blockIdx.x * 128;

    float acc[2][8][4];
    #pragma unroll
    for (int i = 0; i < 2; i++)
        #pragma unroll
        for (int j = 0; j < 8; j++)
            #pragma unroll
            for (int q = 0; q < 4; q++) acc[i][j][q] = 0.f;

    auto load_stage = [&](int c) {
        int s = c % 3;
        #pragma unroll
        for (int p = 0; p < 2; p++) {
            int idx = tid + p * 256;
            int r = idx >> 2, c4 = idx & 3;
            cpa16(s2u(&As[s][r][c4 * 4]), &A[(size_t)(row0 + r) * 1024 + c * 16 + c4 * 4]);
            cpa16(s2u(&Bs[s][r][c4 * 4]), &Bt[(size_t)(col0 + r) * 1024 + c * 16 + c4 * 4]);
        }
        cpcommit();
    };

    load_stage(0); load_stage(1);

    for (int c = 0; c < 64; c++) {
        int s = c % 3;
        if (c < 63) cpwait<1>(); else cpwait<0>();
        __syncthreads();

        #pragma unroll
        for (int k8 = 0; k8 < 16; k8 += 8) {
            uint32_t a[2][4];
            #pragma unroll
            for (int i = 0; i < 2; i++) {
                int r = warpm * 32 + i * 16 + gr;
                int cc = k8 + tq;
                a[i][0] = __float_as_uint(As[s][r][cc]);
                a[i][1] = __float_as_uint(As[s][r + 8][cc]);
                a[i][2] = __float_as_uint(As[s][r][cc + 4]);
                a[i][3] = __float_as_uint(As[s][r + 8][cc + 4]);
            }
            #pragma unroll
            for (int j = 0; j < 8; j++) {
                int nb = warpn * 64 + j * 8 + gr;
                uint32_t b[2];
                b[0] = __float_as_uint(Bs[s][nb][k8 + tq]);
                b[1] = __float_as_uint(Bs[s][nb][k8 + 4 + tq]);
                mma8(acc[0][j], a[0], b);
                mma8(acc[1][j], a[1], b);
            }
        }
        if (c + 2 < 64) load_stage(c + 2);
    }

    // ---- epilogue ----
    #pragma unroll
    for (int i = 0; i < 2; i++) {
        #pragma unroll
        for (int half = 0; half < 2; half++) {
            int m = row0 + warpm * 32 + i * 16 + gr + half * 8;
            #pragma unroll
            for (int j = 0; j < 8; j++) {
                int col = col0 + warpn * 64 + j * 8 + 2 * tq;
                float v0 = acc[i][j][half * 2 + 0] + __ldg(&bias[col]);
                float v1 = acc[i][j][half * 2 + 1] + __ldg(&bias[col + 1]);
                if (MODE == 1) {
                    *(float2*)&Cout[(size_t)m * 1024 + col] = make_float2(v0, v1);
                } else {
                    int which = col >> 10;
                    int d = col & 1023, h = d >> 6, dd = d & 63;
                    int b = m >> 11, t = m & 2047;
                    if (which != 2) { v0 = f2tf(v0); v1 = f2tf(v1); }  // q,k pre-round
                    float* dst = (which == 0) ? g_q : (which == 1) ? g_k : g_v;
                    *(float2*)&dst[((size_t)(b * NH + h) * T_ + t) * HD + dd] =
                        make_float2(v0, v1);
                }
            }
        }
    }
}

// ======================= scores + exp + rowsum ==============================
// Tile 128 q x 128 s, K=64 single shot. E = exp(score/8) -> wts; rowsums atomic.
__global__ void __launch_bounds__(256, 2) attn_scores(float* __restrict__ wts) {
    extern __shared__ float sm[];
    float* Qs = sm;               // [128][68]
    float* Ks = sm + 128 * 68;    // [128][68]

    int tid = threadIdx.x, wid = tid >> 5, lane = tid & 31;
    int gr = lane >> 2, tq = lane & 3;
    int warpm = wid & 3, warpn = wid >> 2;
    int s0 = blockIdx.x * 128, r0 = blockIdx.y * 128, bh = blockIdx.z;

    const float* qh = g_q + ((size_t)bh * T_ + r0) * HD;
    const float* kh = g_k + ((size_t)bh * T_ + s0) * HD;
    #pragma unroll
    for (int p = 0; p < 8; p++) {
        int idx = tid + p * 256;
        int r = idx >> 4, c4 = idx & 15;
        cpa16(s2u(&Qs[r * 68 + c4 * 4]), qh + (size_t)r * HD + c4 * 4);
        cpa16(s2u(&Ks[r * 68 + c4 * 4]), kh + (size_t)r * HD + c4 * 4);
    }
    cpcommit(); cpwait<0>();
    __syncthreads();

    float acc[2][8][4];
    #pragma unroll
    for (int i = 0; i < 2; i++)
        #pragma unroll
        for (int j = 0; j < 8; j++)
            #pragma unroll
            for (int q = 0; q < 4; q++) acc[i][j][q] = 0.f;

    #pragma unroll
    for (int k8 = 0; k8 < 64; k8 += 8) {
        uint32_t a[2][4];
        #pragma unroll
        for (int i = 0; i < 2; i++) {
            int r = warpm * 32 + i * 16 + gr;
            int cc = k8 + tq;
            a[i][0] = __float_as_uint(Qs[r * 68 + cc]);
            a[i][1] = __float_as_uint(Qs[(r + 8) * 68 + cc]);
            a[i][2] = __float_as_uint(Qs[r * 68 + cc + 4]);
            a[i][3] = __float_as_uint(Qs[(r + 8) * 68 + cc + 4]);
        }
        #pragma unroll
        for (int j = 0; j < 8; j++) {
            int nb = warpn * 64 + j * 8 + gr;
            uint32_t b[2];
            b[0] = __float_as_uint(Ks[nb * 68 + k8 + tq]);
            b[1] = __float_as_uint(Ks[nb * 68 + k8 + 4 + tq]);
            mma8(acc[0][j], a[0], b);
            mma8(acc[1][j], a[1], b);
        }
    }

    // exp + store + rowsum
    #pragma unroll
    for (int i = 0; i < 2; i++) {
        #pragma unroll
        for (int half = 0; half < 2; half++) {
            int r = r0 + warpm * 32 + i * 16 + gr + half * 8;
            float sum = 0.f;
            float* wr = wts + ((size_t)bh * T_ + r) * T_;
            #pragma unroll
            for (int j = 0; j < 8; j++) {
                int col = s0 + warpn * 64 + j * 8 + 2 * tq;
                float e0 = __expf(0.125f * acc[i][j][half * 2 + 0]);
                float e1 = __expf(0.125f * acc[i][j][half * 2 + 1]);
                sum += e0 + e1;
                *(float2*)&wr[col] = make_float2(e0, e1);
            }
            sum += __shfl_xor_sync(0xffffffffu, sum, 1);
            sum += __shfl_xor_sync(0xffffffffu, sum, 2);
            if (tq == 0) atomicAdd(&g_rowsum[(size_t)bh * T_ + r], sum);
        }
    }
}

// ======================= AV GEMM (normalize + writeback) ====================
// Tile 128 t x 64 dd, K=2048 (128 BK=16 chunks), 3-stage, 1 sync/iter.
// E loaded by LDG (1 iter ahead), normalized; exact writeback + tf32 smem copy.
#define AVS 20
__global__ void __launch_bounds__(256, 2) av_gemm(float* __restrict__ wts) {
    extern __shared__ float sm[];
    float (*Es)[128][AVS] = (float(*)[128][AVS])sm;
    float (*Vs)[64][AVS]  = (float(*)[64][AVS])(sm + 3 * 128 * AVS);
    float* inv = sm + 3 * 128 * AVS + 3 * 64 * AVS;

    int tid = threadIdx.x, wid = tid >> 5, lane = tid & 31;
    int gr = lane >> 2, tq = lane & 3;
    int warpm = wid & 3, warpn = wid >> 2;
    int r0 = blockIdx.x * 128, bh = blockIdx.y;

    if (tid < 128) inv[tid] = 1.f / g_rowsum[(size_t)bh * T_ + r0 + tid];

    float* wb = wts + ((size_t)bh * T_ + r0) * T_;
    const float* vtb = g_vt + (size_t)bh * HD * T_;

    int ar0 = tid >> 1, ac0 = (tid & 1) * 8;   // A: 2 float4 per thread
    float4 pre[2];
    auto ldA = [&](int c) {
        pre[0] = *(const float4*)&wb[(size_t)ar0 * T_ + c * 16 + ac0];
        pre[1] = *(const float4*)&wb[(size_t)ar0 * T_ + c * 16 + ac0 + 4];
    };
    auto stA = [&](int c) {   // needs inv[] ready (after first syncthreads)
        int s = c % 3;
        float iv = inv[ar0];
        #pragma unroll
        for (int u = 0; u < 2; u++) {
            float4 w = pre[u];
            w.x *= iv; w.y *= iv; w.z *= iv; w.w *= iv;
            *(float4*)&wb[(size_t)ar0 * T_ + c * 16 + ac0 + u * 4] = w;
            w.x = f2tf(w.x); w.y = f2tf(w.y); w.z = f2tf(w.z); w.w = f2tf(w.w);
            *(float4*)&Es[s][ar0][ac0 + u * 4] = w;
        }
    };
    auto ldB = [&](int c) {
        int s = c % 3;
        int r = tid >> 2, c4 = tid & 3;
        cpa16(s2u(&Vs[s][r][c4 * 4]), vtb + (size_t)r * T_ + c * 16 + c4 * 4);
        cpcommit();
    };

    float acc[2][4][4];
    #pragma unroll
    for (int i = 0; i < 2; i++)
        #pragma unroll
        for (int j = 0; j < 4; j++)
            #pragma unroll
            for (int q = 0; q < 4; q++) acc[i][j][q] = 0.f;

    ldA(0); ldB(0); ldB(1);
    __syncthreads();            // inv visible
    stA(0);
    ldA(1); stA(1);
    ldA(2);

    for (int c = 0; c < 128; c++) {
        int s = c % 3;
        if (c < 127) cpwait<1>(); else cpwait<0>();
        __syncthreads();

        #pragma unroll
        for (int k8 = 0; k8 < 16; k8 += 8) {
            uint32_t a[2][4];
            #pragma unroll
            for (int i = 0; i < 2; i++) {
                int r = warpm * 32 + i * 16 + gr;
                int cc = k8 + tq;
                a[i][0] = __float_as_uint(Es[s][r][cc]);
                a[i][1] = __float_as_uint(Es[s][r + 8][cc]);
                a[i][2] = __float_as_uint(Es[s][r][cc + 4]);
                a[i][3] = __float_as_uint(Es[s][r + 8][cc + 4]);
            }
            #pragma unroll
            for (int j = 0; j < 4; j++) {
                int nb = warpn * 32 + j * 8 + gr;
                uint32_t b[2];
                b[0] = __float_as_uint(Vs[s][nb][k8 + tq]);
                b[1] = __float_as_uint(Vs[s][nb][k8 + 4 + tq]);
                mma8(acc[0][j], a[0], b);
                mma8(acc[1][j], a[1], b);
            }
        }
        if (c + 2 < 128) {
            stA(c + 2);
            if (c + 3 < 128) ldA(c + 3);
            ldB(c + 2);
        }
    }

    int b = bh >> 4, h = bh & 15;
    #pragma unroll
    for (int i = 0; i < 2; i++) {
        #pragma unroll
        for (int half = 0; half < 2; half++) {
            int t = r0 + warpm * 32 + i * 16 + gr + half * 8;
            float* orow = g_ao + (size_t)(b * T_ + t) * D_MODEL + h * HD;
            #pragma unroll
            for (int j = 0; j < 4; j++) {
                int dd = warpn * 32 + j * 8 + 2 * tq;
                *(float2*)&orow[dd] = make_float2(
                    f2tf(acc[i][j][half * 2 + 0]), f2tf(acc[i][j][half * 2 + 1]));
            }
        }
    }
}

// ===========================================================================
extern "C" void kernel_launch(void* const* d_in, const int* in_sizes, int n_in,
                              void* d_out, int out_size) {
    const float* x    = (const float*)d_in[0];
    const float* Wqkv = (const float*)d_in[1];
    const float* bqkv = (const float*)d_in[2];
    const float* Wo   = (const float*)d_in[3];
    const float* bo   = (const float*)d_in[4];

    float* y   = (float*)d_out;                         // [B,T,D]
    float* wts = (float*)d_out + (size_t)BT * D_MODEL;  // [B,H,T,T]

    const int GB_SMEM = 2 * 3 * 128 * GBS * 4;              // 61440
    const int AV_SMEM = (3 * 128 * AVS + 3 * 64 * AVS + 128) * 4;  // 46592
    const int SC_SMEM = 2 * 128 * 68 * 4;                   // 69632
    cudaFuncSetAttribute(gemm_big<0>, cudaFuncAttributeMaxDynamicSharedMemorySize, GB_SMEM);
    cudaFuncSetAttribute(gemm_big<1>, cudaFuncAttributeMaxDynamicSharedMemorySize, GB_SMEM);
    cudaFuncSetAttribute(attn_scores, cudaFuncAttributeMaxDynamicSharedMemorySize, SC_SMEM);
    cudaFuncSetAttribute(av_gemm,     cudaFuncAttributeMaxDynamicSharedMemorySize, AV_SMEM);

    float *wt_p = nullptr, *wot_p = nullptr, *ao_p = nullptr, *x_p = nullptr;
    cudaGetSymbolAddress((void**)&wt_p,  g_wt);
    cudaGetSymbolAddress((void**)&wot_p, g_wot);
    cudaGetSymbolAddress((void**)&ao_p,  g_ao);
    cudaGetSymbolAddress((void**)&x_p,   g_x);

    zero_rowsum<<<BH * T_ / 256, 256>>>();
    cvt_x<<<BT * D_MODEL / 1024, 256>>>(x);
    transpose_w<<<dim3(96, 32), dim3(32, 8)>>>(Wqkv, wt_p, 1024, 3072);
    transpose_w<<<dim3(32, 32), dim3(32, 8)>>>(Wo, wot_p, 1024, 1024);

    gemm_big<0><<<dim3(24, 32), 256, GB_SMEM>>>(x_p, wt_p, bqkv, nullptr);
    transpose_v<<<dim3(2, 64, 32), dim3(32, 8)>>>();

    attn_scores<<<dim3(16, 16, 32), 256, SC_SMEM>>>(wts);
    av_gemm<<<dim3(16, 32), 256, AV_SMEM>>>(wts);
    gemm_big<1><<<dim3(8, 32), 256, GB_SMEM>>>(ao_p, wot_p, bo, y);
}